// round 2
// baseline (speedup 1.0000x reference)
#include <cuda_runtime.h>
#include <math.h>

// Problem constants (fixed by the dataset)
#define BB 4
#define NN 512
#define NZV 95
#define TBL (NZV * 25)   // 2375 floats per staged slab

#define F_CUTOFF 15.0f
#define F_SON    12.0f
#define F_SOFF   15.0f
#define F_A1   0.4145f
#define F_A2   4.8593f
#define F_S6   1.0f
#define F_S8   1.2177f
#define F_K1   16.0f
#define F_K3   4.0f
#define F_BOHR 1.8897261258369282f
#define F_H2EV 27.211386245988f

// Global scratch (allocation-free rules: __device__ globals)
__device__ float g_cn[BB * NN];
__device__ float g_partial[BB * NN];

__device__ __forceinline__ int clampz(int z) {
    z = z < 0 ? 0 : z;
    return z > (NZV - 1) ? (NZV - 1) : z;
}

__device__ __forceinline__ float block_reduce_f(float v, float* s_red) {
    int t = threadIdx.x;
    #pragma unroll
    for (int o = 16; o > 0; o >>= 1) v += __shfl_down_sync(0xffffffffu, v, o);
    if ((t & 31) == 0) s_red[t >> 5] = v;
    __syncthreads();
    if (t < 32) {
        v = (t < (int)(blockDim.x >> 5)) ? s_red[t] : 0.0f;
        #pragma unroll
        for (int o = 16; o > 0; o >>= 1) v += __shfl_down_sync(0xffffffffu, v, o);
    }
    return v;  // valid in thread 0
}

// ---------------------------------------------------------------------------
// Kernel 1: coordination numbers. One block per (b,i).
// ---------------------------------------------------------------------------
__global__ __launch_bounds__(128) void cn_kernel(
    const float* __restrict__ coord,
    const int*   __restrict__ numbers,
    const float* __restrict__ rcov)
{
    __shared__ float s_x[NN], s_y[NN], s_z[NN];
    __shared__ float s_rc[NN];
    __shared__ float s_red[4];

    int bid = blockIdx.x;           // b*NN + i
    int b = bid / NN;
    int i = bid % NN;

    const float* cb = coord + (size_t)b * NN * 3;
    for (int j = threadIdx.x; j < NN; j += blockDim.x) {
        s_x[j] = cb[j * 3 + 0];
        s_y[j] = cb[j * 3 + 1];
        s_z[j] = cb[j * 3 + 2];
        s_rc[j] = __ldg(&rcov[clampz(numbers[b * NN + j])]);
    }
    __syncthreads();

    float xi = s_x[i], yi = s_y[i], zi_ = s_z[i];
    float rci = s_rc[i];

    float sum = 0.0f;
    for (int j = threadIdx.x; j < NN; j += blockDim.x) {
        if (j == i) continue;
        float dx = xi - s_x[j];
        float dy = yi - s_y[j];
        float dz = zi_ - s_z[j];
        float r2 = dx * dx + dy * dy + dz * dz;
        float r_ang = sqrtf(r2);
        if (r_ang > F_CUTOFF) continue;
        float rco = rci + s_rc[j];
        float r = r_ang * F_BOHR;
        // 1/(1+exp(-K1*(rco/r - 1)))
        float arg = -F_K1 * (rco / r - 1.0f);
        sum += 1.0f / (1.0f + __expf(arg));
    }
    float tot = block_reduce_f(sum, s_red);
    if (threadIdx.x == 0) g_cn[bid] = tot;
}

// ---------------------------------------------------------------------------
// Kernel 2: pair energies. One block per (b,i); zi fixed per block so the
// c6ab[zi,:,:,:], cn_ref[zi,:,:,:], cn_ref[:,zi,:,:] slabs are staged in SMEM.
// ---------------------------------------------------------------------------
__global__ __launch_bounds__(128) void energy_kernel(
    const float* __restrict__ coord,
    const int*   __restrict__ numbers,
    const float* __restrict__ r4r2,
    const float* __restrict__ c6ab,
    const float* __restrict__ cn_ref)
{
    __shared__ float s_c6[TBL];
    __shared__ float s_cni[TBL];
    __shared__ float s_cnj[TBL];
    __shared__ float s_x[NN], s_y[NN], s_z[NN];
    __shared__ float s_cn[NN];
    __shared__ float s_rr[NN];
    __shared__ int   s_zj[NN];
    __shared__ float s_red[4];

    int bid = blockIdx.x;           // b*NN + i
    int b = bid / NN;
    int i = bid % NN;

    int zi = clampz(numbers[b * NN + i]);

    // Stage tables: index t = a*25 + (k*5+l), a = candidate zj
    for (int t = threadIdx.x; t < TBL; t += blockDim.x) {
        int a = t / 25;
        int rem = t - a * 25;
        s_c6[t]  = __ldg(&c6ab  [((size_t)zi * NZV + a) * 25 + rem]);
        s_cni[t] = __ldg(&cn_ref[((size_t)zi * NZV + a) * 25 + rem]);
        s_cnj[t] = __ldg(&cn_ref[((size_t)a * NZV + zi) * 25 + rem]);
    }

    const float* cb = coord + (size_t)b * NN * 3;
    for (int j = threadIdx.x; j < NN; j += blockDim.x) {
        s_x[j] = cb[j * 3 + 0];
        s_y[j] = cb[j * 3 + 1];
        s_z[j] = cb[j * 3 + 2];
        int zj = clampz(numbers[b * NN + j]);
        s_zj[j] = zj;
        s_rr[j] = __ldg(&r4r2[zj]);
        s_cn[j] = g_cn[b * NN + j];
    }
    __syncthreads();

    float xi = s_x[i], yi = s_y[i], zc = s_z[i];
    float cni_val = s_cn[i];
    float rri = s_rr[i];

    float esum = 0.0f;
    for (int j = threadIdx.x; j < NN; j += blockDim.x) {
        if (j == i) continue;
        float dx = xi - s_x[j];
        float dy = yi - s_y[j];
        float dz = zc - s_z[j];
        float r2 = dx * dx + dy * dy + dz * dz;
        float r_ang = sqrtf(r2);
        if (r_ang > F_CUTOFF) continue;

        int zj = s_zj[j];
        float cnj_val = s_cn[j];

        const float* pc6  = s_c6  + zj * 25;
        const float* pcni = s_cni + zj * 25;
        const float* pcnj = s_cnj + zj * 25;

        float c6s = 0.0f, wsum = 0.0f;
        #pragma unroll
        for (int k = 0; k < 5; k++) {
            #pragma unroll
            for (int l = 0; l < 5; l++) {
                float c6r = pc6[k * 5 + l];
                float d1 = cni_val - pcni[k * 5 + l];
                float d2 = cnj_val - pcnj[l * 5 + k];   // cn_ref[zj][zi] transposed
                float w = (c6r > 0.0f)
                        ? __expf(-F_K3 * (d1 * d1 + d2 * d2)) : 0.0f;
                wsum += w;
                c6s = fmaf(c6r, w, c6s);
            }
        }
        float c6 = c6s / (wsum + 1e-20f);

        float rr = rri * s_rr[j];
        float c8 = 3.0f * c6 * rr;
        float r0 = sqrtf(3.0f * rr);
        float f  = fmaf(F_A1, r0, F_A2);
        float f2 = f * f;
        float f6 = f2 * f2 * f2;
        float f8 = f6 * f2;

        float rb2 = r2 * (F_BOHR * F_BOHR);
        float r6 = rb2 * rb2 * rb2;
        float rb = r_ang * F_BOHR;
        float r8 = r6 * rb * rb;

        float e = F_S6 * c6 / (r6 + f6) + F_S8 * c8 / (r8 + f8);

        // smooth switch
        float x = (r_ang - F_SON) * (1.0f / (F_SOFF - F_SON));
        x = fminf(fmaxf(x, 0.0f), 1.0f);
        float sw = 1.0f - x * x * (3.0f - 2.0f * x);

        esum += e * sw;
    }

    float tot = block_reduce_f(esum, s_red);
    if (threadIdx.x == 0) g_partial[bid] = tot;
}

// ---------------------------------------------------------------------------
// Kernel 3: deterministic final reduction. One block per batch.
// ---------------------------------------------------------------------------
__global__ __launch_bounds__(128) void finalize_kernel(float* __restrict__ out)
{
    __shared__ double s_red[128];
    int b = blockIdx.x;
    double v = 0.0;
    for (int t = threadIdx.x; t < NN; t += blockDim.x)
        v += (double)g_partial[b * NN + t];
    s_red[threadIdx.x] = v;
    __syncthreads();
    for (int o = 64; o > 0; o >>= 1) {
        if (threadIdx.x < o) s_red[threadIdx.x] += s_red[threadIdx.x + o];
        __syncthreads();
    }
    if (threadIdx.x == 0)
        out[b] = (float)(-0.5 * s_red[0] * (double)F_H2EV);
}

extern "C" void kernel_launch(void* const* d_in, const int* in_sizes, int n_in,
                              void* d_out, int out_size)
{
    const float* coord   = (const float*)d_in[0];
    const int*   numbers = (const int*)  d_in[1];   // jax x64 disabled -> int32
    const float* rcov    = (const float*)d_in[2];
    const float* r4r2    = (const float*)d_in[3];
    const float* c6ab    = (const float*)d_in[4];
    const float* cn_ref  = (const float*)d_in[5];
    float* out = (float*)d_out;

    cn_kernel<<<BB * NN, 128>>>(coord, numbers, rcov);
    energy_kernel<<<BB * NN, 128>>>(coord, numbers, r4r2, c6ab, cn_ref);
    finalize_kernel<<<BB, 128>>>(out);
}

// round 4
// speedup vs baseline: 1.0462x; 1.0462x over previous
#include <cuda_runtime.h>
#include <math.h>

// Problem constants (fixed by the dataset)
#define BB 4
#define NN 512
#define NZV 95
#define TBL (NZV * 25)    // 2375 entries per staged table
#define JT 8              // j-tiles in cn kernel
#define ISPL 2            // i-split in energy kernel
#define NPART (BB * NZV * ISPL)

#define F_CUTOFF 15.0f
#define F_A1   0.4145f
#define F_A2   4.8593f
#define F_S8   1.2177f
#define F_K1   16.0f
#define F_K3   4.0f
#define F_BOHR 1.8897261258369282f
#define F_BOHR2 (F_BOHR * F_BOHR)
#define F_H2EV 27.211386245988f

// Global scratch (allocation-free rules: __device__ globals)
__device__ float  g_cnp[BB * JT * NN];    // cn partials per j-tile
__device__ float4 g_spos[BB * NN];        // species-sorted (x,y,z,cn)
__device__ float  g_srr[BB * NN];         // sorted r4r2[z]
__device__ int    g_szj[BB * NN];         // sorted species
__device__ int    g_sorig[BB * NN];       // sorted original index
__device__ int    g_goff[BB * 96];        // species bucket offsets (off[95]=512)
__device__ float  g_partial[NPART];       // per-(b,zi,split) energy partials

__device__ __forceinline__ int clampz(int z) {
    z = z < 0 ? 0 : z;
    return z > (NZV - 1) ? (NZV - 1) : z;
}

// ---------------------------------------------------------------------------
// Kernel 1: CN partials. grid = BB*JT, 512 threads, thread = atom i,
// block covers j-tile of 64 atoms staged in smem.
// ---------------------------------------------------------------------------
__global__ __launch_bounds__(512) void cn_kernel(
    const float* __restrict__ coord,
    const int*   __restrict__ numbers,
    const float* __restrict__ rcov)
{
    __shared__ float4 s_j[NN / JT];   // x,y,z,rcov for this j-tile

    int b  = blockIdx.x >> 3;         // JT == 8
    int jt = blockIdx.x & 7;
    int j0 = jt * (NN / JT);
    int t  = threadIdx.x;

    if (t < NN / JT) {
        int j = j0 + t;
        const float* cb = coord + ((size_t)b * NN + j) * 3;
        s_j[t] = make_float4(cb[0], cb[1], cb[2],
                             __ldg(&rcov[clampz(numbers[b * NN + j])]));
    }
    __syncthreads();

    int i = t;
    const float* ci = coord + ((size_t)b * NN + i) * 3;
    float xi = ci[0], yi = ci[1], zi_ = ci[2];
    float rci = __ldg(&rcov[clampz(numbers[b * NN + i])]);

    float sum = 0.0f;
    #pragma unroll 4
    for (int jj = 0; jj < NN / JT; jj++) {
        int j = j0 + jj;
        if (j == i) continue;
        float4 p = s_j[jj];
        float dx = xi - p.x, dy = yi - p.y, dz = zi_ - p.z;
        float r2 = dx * dx + dy * dy + dz * dz;
        float r_ang = sqrtf(r2);
        if (r_ang > F_CUTOFF) continue;
        float rco = rci + p.w;
        float a = F_K1 * (__fdividef(rco, r_ang * F_BOHR) - 1.0f);
        // sigmoid(a); IEEE div handles exp overflow (-> 0) correctly
        sum += 1.0f / (1.0f + __expf(-a));
    }
    g_cnp[(size_t)blockIdx.x * NN + i] = sum;
}

// ---------------------------------------------------------------------------
// Kernel 2: combine CN partials + deterministic stable species sort.
// grid = BB, 512 threads, thread = atom.
// ---------------------------------------------------------------------------
__global__ __launch_bounds__(512) void sort_kernel(
    const float* __restrict__ coord,
    const int*   __restrict__ numbers,
    const float* __restrict__ r4r2)
{
    __shared__ int s_z[NN];
    __shared__ int s_hist[96];
    __shared__ int s_off[96];

    int b = blockIdx.x;
    int t = threadIdx.x;

    float cn = 0.0f;
    #pragma unroll
    for (int jt = 0; jt < JT; jt++)
        cn += g_cnp[((size_t)b * JT + jt) * NN + t];

    int z = clampz(numbers[b * NN + t]);
    s_z[t] = z;
    if (t < 96) s_hist[t] = 0;
    __syncthreads();
    atomicAdd(&s_hist[z], 1);
    __syncthreads();
    if (t == 0) {
        int acc = 0;
        for (int a = 0; a < NZV; a++) { s_off[a] = acc; acc += s_hist[a]; }
        s_off[95] = acc;   // == NN
    }
    __syncthreads();

    // stable rank: count of same-species atoms before me
    int rank = 0;
    for (int j = 0; j < t; j++) rank += (s_z[j] == z);
    int p = s_off[z] + rank;

    const float* ci = coord + ((size_t)b * NN + t) * 3;
    g_spos [b * NN + p] = make_float4(ci[0], ci[1], ci[2], cn);
    g_srr  [b * NN + p] = __ldg(&r4r2[z]);
    g_szj  [b * NN + p] = z;
    g_sorig[b * NN + p] = t;
    if (t < 96) g_goff[b * 96 + t] = s_off[t];
}

// ---------------------------------------------------------------------------
// Kernel 3: pair energies. block per (b, zi, i-split); zi uniform per block.
// 512 threads, thread = sorted-j slot (its species/coords/cn live in regs).
// ---------------------------------------------------------------------------
__global__ __launch_bounds__(512) void energy_kernel(
    const float* __restrict__ c6ab,
    const float* __restrict__ cn_ref)
{
    int blk  = blockIdx.x;               // b*(95*ISPL) + zi*ISPL + s
    int b    = blk / (NZV * ISPL);
    int rest = blk - b * (NZV * ISPL);
    int zi   = rest / ISPL;
    int s    = rest - zi * ISPL;
    int t    = threadIdx.x;

    int off = __ldg(&g_goff[b * 96 + zi]);
    int end = __ldg(&g_goff[b * 96 + zi + 1]);
    int n   = end - off;
    if (n <= s) {                        // no i's for this block: emit 0
        if (t == 0) g_partial[blk] = 0.0f;
        return;
    }

    __shared__ float4 s_tab[TBL];        // {c6, cni_ref, cnj_refT, 0}
    __shared__ float4 s_pos[NN];         // sorted (x,y,z,cn)
    __shared__ float  s_rr[NN];
    __shared__ int    s_zj[NN];
    __shared__ int    s_orig[NN];
    __shared__ float  s_red[16];

    // Stage interleaved tables; cnj stored pre-transposed so all three share
    // the same inner index r = k*5+l.
    const float* c6row  = c6ab   + (size_t)zi * NZV * 25;
    const float* cnirow = cn_ref + (size_t)zi * NZV * 25;
    for (int q = t; q < TBL; q += 512) {
        int a = q / 25;
        int r = q - 25 * a;
        int k = r / 5, l = r - 5 * k;
        float cnj = __ldg(&cn_ref[((size_t)a * NZV + zi) * 25 + l * 5 + k]);
        s_tab[q] = make_float4(__ldg(&c6row[q]), __ldg(&cnirow[q]), cnj, 0.0f);
    }
    // Stage sorted atom records (one per thread)
    s_pos [t] = g_spos [b * NN + t];
    s_rr  [t] = g_srr  [b * NN + t];
    s_zj  [t] = g_szj  [b * NN + t];
    s_orig[t] = g_sorig[b * NN + t];
    __syncthreads();

    // my j-side data, fixed for the whole block
    float4 pj = s_pos[t];
    float rrj = s_rr[t];
    int   zj  = s_zj[t];
    int   jor = s_orig[t];
    const float4* ptab = s_tab + zj * 25;
    float cnj_v = pj.w;

    float esum = 0.0f;
    for (int ii = s; ii < n; ii += ISPL) {
        int sp = off + ii;               // block-uniform -> broadcast LDS
        float4 pi = s_pos[sp];
        float rri = s_rr[sp];
        int   ior = s_orig[sp];

        float dx = pi.x - pj.x, dy = pi.y - pj.y, dz = pi.z - pj.z;
        float r2 = dx * dx + dy * dy + dz * dz;
        float r_ang = sqrtf(r2);
        if (jor == ior || r_ang > F_CUTOFF) continue;

        float cni_v = pi.w;
        float w0 = 0.0f, w1 = 0.0f, c60 = 0.0f, c61 = 0.0f;
        #pragma unroll
        for (int r = 0; r < 25; r++) {
            float4 tv = ptab[r];
            float d1 = cni_v - tv.y;
            float d2 = cnj_v - tv.z;
            float ss = fmaf(d2, d2, d1 * d1);
            float w  = __expf(-F_K3 * ss);
            w = (tv.x > 0.0f) ? w : 0.0f;
            if (r & 1) { w1 += w; c61 = fmaf(tv.x, w, c61); }
            else       { w0 += w; c60 = fmaf(tv.x, w, c60); }
        }
        float c6 = __fdividef(c60 + c61, w0 + w1 + 1e-20f);

        float rr = rri * rrj;
        float c8 = 3.0f * c6 * rr;
        float r0 = sqrtf(3.0f * rr);
        float f  = fmaf(F_A1, r0, F_A2);
        float f2 = f * f;
        float f6 = f2 * f2 * f2;
        float f8 = f6 * f2;

        float rb2 = r2 * F_BOHR2;
        float r6 = rb2 * rb2 * rb2;
        float r8 = r6 * rb2;             // r6 * (r_ang*BOHR)^2 exactly

        float e = __fdividef(c6, r6 + f6) + F_S8 * __fdividef(c8, r8 + f8);

        float x = (r_ang - 12.0f) * (1.0f / 3.0f);
        x = __saturatef(x);
        float sw = 1.0f - x * x * (3.0f - 2.0f * x);

        esum = fmaf(e, sw, esum);
    }

    // block reduce (deterministic)
    #pragma unroll
    for (int o = 16; o > 0; o >>= 1) esum += __shfl_down_sync(0xffffffffu, esum, o);
    if ((t & 31) == 0) s_red[t >> 5] = esum;
    __syncthreads();
    if (t < 32) {
        float v = (t < 16) ? s_red[t] : 0.0f;
        #pragma unroll
        for (int o = 8; o > 0; o >>= 1) v += __shfl_down_sync(0xffffffffu, v, o);
        if (t == 0) g_partial[blk] = v;
    }
}

// ---------------------------------------------------------------------------
// Kernel 4: deterministic final reduction. grid = BB.
// ---------------------------------------------------------------------------
__global__ __launch_bounds__(256) void finalize_kernel(float* __restrict__ out)
{
    __shared__ double s_red[256];
    int b = blockIdx.x;
    int t = threadIdx.x;
    const int nper = NZV * ISPL;         // 190
    double v = 0.0;
    for (int q = t; q < nper; q += 256)
        v += (double)g_partial[b * nper + q];
    s_red[t] = v;
    __syncthreads();
    for (int o = 128; o > 0; o >>= 1) {
        if (t < o) s_red[t] += s_red[t + o];
        __syncthreads();
    }
    if (t == 0)
        out[b] = (float)(-0.5 * s_red[0] * (double)F_H2EV);
}

extern "C" void kernel_launch(void* const* d_in, const int* in_sizes, int n_in,
                              void* d_out, int out_size)
{
    const float* coord   = (const float*)d_in[0];
    const int*   numbers = (const int*)  d_in[1];
    const float* rcov    = (const float*)d_in[2];
    const float* r4r2    = (const float*)d_in[3];
    const float* c6ab    = (const float*)d_in[4];
    const float* cn_ref  = (const float*)d_in[5];
    float* out = (float*)d_out;

    cn_kernel     <<<BB * JT, 512>>>(coord, numbers, rcov);
    sort_kernel   <<<BB, 512>>>(coord, numbers, r4r2);
    energy_kernel <<<BB * NZV * ISPL, 512>>>(c6ab, cn_ref);
    finalize_kernel<<<BB, 256>>>(out);
}

// round 7
// speedup vs baseline: 1.3596x; 1.2995x over previous
#include <cuda_runtime.h>
#include <math.h>

// Problem constants (fixed by the dataset)
#define BB 4
#define NN 512
#define NZV 95
#define TBL (NZV * 25)    // 2375 entries per staged table
#define JT 32             // j-tiles in cn kernel (BB*JT = 128 blocks)
#define ISPL 2            // i-split in energy kernel
#define NBLK (BB * NZV * ISPL)
#define NPERB (NZV * ISPL)

#define F_A1   0.4145f
#define F_A2   4.8593f
#define F_S8   1.2177f
#define F_K1   16.0f
#define F_K3   4.0f
#define F_LOG2E 1.4426950408889634f
#define F_K3L   (F_K3 * F_LOG2E)
#define F_BOHR 1.8897261258369282f
#define F_BOHR2 (F_BOHR * F_BOHR)
#define F_H2EV 27.211386245988f

// Global scratch (allocation-free rules: __device__ globals)
__device__ float  g_cnp[BB * JT * NN];    // cn partials per j-tile
__device__ float4 g_spos[BB * NN];        // species-sorted (x,y,z,cn)
__device__ float  g_srr[BB * NN];         // sorted r4r2[z]
__device__ int    g_szj[BB * NN];         // sorted species
__device__ int    g_goff[BB * 96];        // species bucket offsets (off[95]=512)
__device__ float  g_partial[NBLK];        // per-(b,zi,split) energy partials
__device__ int    g_cnt;                  // zero-init; self-resetting

__device__ __forceinline__ int clampz(int z) {
    z = z < 0 ? 0 : z;
    return z > (NZV - 1) ? (NZV - 1) : z;
}

__device__ __forceinline__ float ex2f(float x) {
    float r;
    asm("ex2.approx.ftz.f32 %0, %1;" : "=f"(r) : "f"(x));
    return r;
}

// ---------------------------------------------------------------------------
// Kernel 1: CN partials. grid = BB*JT (128), 512 threads, thread = atom i,
// block covers a j-tile of 16 atoms staged in smem.
// ---------------------------------------------------------------------------
__global__ __launch_bounds__(512) void cn_kernel(
    const float* __restrict__ coord,
    const int*   __restrict__ numbers,
    const float* __restrict__ rcov)
{
    __shared__ float4 s_j[NN / JT];   // 16 atoms: x,y,z,rcov

    int b  = blockIdx.x >> 5;         // JT == 32
    int jt = blockIdx.x & 31;
    int j0 = jt * (NN / JT);
    int t  = threadIdx.x;

    if (t < NN / JT) {
        int j = j0 + t;
        const float* cb = coord + ((size_t)b * NN + j) * 3;
        s_j[t] = make_float4(cb[0], cb[1], cb[2],
                             __ldg(&rcov[clampz(numbers[b * NN + j])]));
    }
    __syncthreads();

    int i = t;
    const float* ci = coord + ((size_t)b * NN + i) * 3;
    float xi = ci[0], yi = ci[1], zi_ = ci[2];
    float rci = __ldg(&rcov[clampz(numbers[b * NN + i])]);

    float sum = 0.0f;
    #pragma unroll
    for (int jj = 0; jj < NN / JT; jj++) {
        int j = j0 + jj;
        if (j == i) continue;
        float4 p = s_j[jj];
        float dx = xi - p.x, dy = yi - p.y, dz = zi_ - p.z;
        float r2 = dx * dx + dy * dy + dz * dz;
        float r_ang = sqrtf(r2);
        if (r_ang > 15.0f) continue;
        float rco = rci + p.w;
        float a = F_K1 * (__fdividef(rco, r_ang * F_BOHR) - 1.0f);
        sum += 1.0f / (1.0f + __expf(-a));   // sigmoid(a)
    }
    g_cnp[(size_t)blockIdx.x * NN + i] = sum;
}

// ---------------------------------------------------------------------------
// Kernel 2: combine CN partials + deterministic stable species sort.
// grid = BB, 512 threads, thread = atom. O(1) rank via match_any + histograms.
// ---------------------------------------------------------------------------
__global__ __launch_bounds__(512) void sort_kernel(
    const float* __restrict__ coord,
    const int*   __restrict__ numbers,
    const float* __restrict__ r4r2)
{
    __shared__ int s_wh[16][96];   // per-warp species histogram -> warp prefix
    __shared__ int s_off[96];      // per-species global offsets

    int b = blockIdx.x;
    int t = threadIdx.x;
    int wid = t >> 5, lane = t & 31;

    float cn = 0.0f;
    #pragma unroll
    for (int jt = 0; jt < JT; jt++)
        cn += g_cnp[((size_t)b * JT + jt) * NN + t];

    int z = clampz(numbers[b * NN + t]);

    for (int q = t; q < 16 * 96; q += 512) (&s_wh[0][0])[q] = 0;
    __syncthreads();

    unsigned m = __match_any_sync(0xffffffffu, z);
    int intra = __popc(m & ((1u << lane) - 1u));
    int leader = __ffs(m) - 1;
    if (lane == leader) s_wh[wid][z] = __popc(m);   // unique (wid,z) writer
    __syncthreads();

    // per-species: exclusive prefix over warps + total
    __shared__ int s_tot[96];
    if (t < 95) {
        int acc = 0;
        #pragma unroll
        for (int w = 0; w < 16; w++) { int c = s_wh[w][t]; s_wh[w][t] = acc; acc += c; }
        s_tot[t] = acc;
    }
    __syncthreads();
    if (t == 0) {
        int acc = 0;
        for (int a = 0; a < NZV; a++) { s_off[a] = acc; acc += s_tot[a]; }
        s_off[95] = acc;   // == NN
    }
    __syncthreads();

    int p = s_off[z] + s_wh[wid][z] + intra;

    const float* ci = coord + ((size_t)b * NN + t) * 3;
    g_spos[b * NN + p] = make_float4(ci[0], ci[1], ci[2], cn);
    g_srr [b * NN + p] = __ldg(&r4r2[z]);
    g_szj [b * NN + p] = z;
    if (t < 96) g_goff[b * 96 + t] = s_off[t];
}

// ---------------------------------------------------------------------------
// Kernel 3: pair energies + fused finalize. block per (b, zi, i-split);
// zi uniform per block. 512 threads, thread = sorted-j slot.
// Weight refactor: w = exp2(A*cni + B*cnj + G + D),
//   A=2*K3*log2e*a, B=2*K3*log2e*bT, G=-K3*log2e*(a^2+b^2) (per term, staged),
//   D=-K3*log2e*(cni^2+cnj^2) (per pair) keeps arg <= 0.
// ---------------------------------------------------------------------------
__global__ __launch_bounds__(512) void energy_kernel(
    const float* __restrict__ c6ab,
    const float* __restrict__ cn_ref,
    float* __restrict__ out)
{
    __shared__ float4 s_tab[TBL];        // {A, B, G, c6}
    __shared__ float  s_red[16];
    __shared__ double s_dred[16];
    __shared__ int    s_last;

    int blk  = blockIdx.x;               // b*(95*ISPL) + zi*ISPL + s
    int b    = blk / NPERB;
    int rest = blk - b * NPERB;
    int zi   = rest / ISPL;
    int s    = rest - zi * ISPL;
    int t    = threadIdx.x;
    int wid = t >> 5, lane = t & 31;

    int off = __ldg(&g_goff[b * 96 + zi]);
    int end = __ldg(&g_goff[b * 96 + zi + 1]);
    int n   = end - off;

    // Stage tables (cnj pre-transposed into the shared inner index r=k*5+l)
    const float* c6row  = c6ab   + (size_t)zi * NZV * 25;
    const float* cnirow = cn_ref + (size_t)zi * NZV * 25;
    for (int q = t; q < TBL; q += 512) {
        int a = q / 25;
        int r = q - 25 * a;
        int k = r / 5, l = r - 5 * k;
        float av = __ldg(&cnirow[q]);
        float bv = __ldg(&cn_ref[((size_t)a * NZV + zi) * 25 + l * 5 + k]);
        float c6 = __ldg(&c6row[q]);
        float A = 2.0f * F_K3L * av;
        float Bv = 2.0f * F_K3L * bv;
        float G = -F_K3L * (av * av + bv * bv);
        if (c6 <= 0.0f) G = -__int_as_float(0x7f800000);  // -inf -> w = 0
        s_tab[q] = make_float4(A, Bv, G, c6);
    }
    __syncthreads();

    // my j-side data (registers for the whole block)
    float4 pj  = __ldg(&g_spos[b * NN + t]);
    float  rrj = __ldg(&g_srr [b * NN + t]);
    int    zj  = __ldg(&g_szj [b * NN + t]);
    float  cnj_v = pj.w;
    float  Lcnj2 = F_K3L * cnj_v * cnj_v;
    const float4* ptab = s_tab + zj * 25;

    float esum = 0.0f;
    for (int ii = s; ii < n; ii += ISPL) {
        int sp = off + ii;                      // block-uniform
        float4 pi  = __ldg(&g_spos[b * NN + sp]);
        float  rri = __ldg(&g_srr [b * NN + sp]);

        float dx = pi.x - pj.x, dy = pi.y - pj.y, dz = pi.z - pj.z;
        float r2 = dx * dx + dy * dy + dz * dz;
        float r_ang = sqrtf(r2);
        if (sp == t || r_ang > 15.0f) continue;

        float cni_v = pi.w;
        float Dp = fmaf(-F_K3L, cni_v * cni_v, -Lcnj2);

        float w0 = 0.0f, w1 = 0.0f, c60 = 0.0f, c61 = 0.0f;
        #pragma unroll
        for (int r = 0; r < 25; r++) {
            float4 tv = ptab[r];
            float arg = fmaf(tv.x, cni_v, fmaf(tv.y, cnj_v, tv.z)) + Dp;
            float w = ex2f(arg);
            if (r & 1) { w1 += w; c61 = fmaf(tv.w, w, c61); }
            else       { w0 += w; c60 = fmaf(tv.w, w, c60); }
        }
        float c6 = __fdividef(c60 + c61, w0 + w1 + 1e-20f);

        float rr = rri * rrj;
        float c8 = 3.0f * c6 * rr;
        float r0 = sqrtf(3.0f * rr);
        float f  = fmaf(F_A1, r0, F_A2);
        float f2 = f * f;
        float f6 = f2 * f2 * f2;
        float f8 = f6 * f2;

        float rb2 = r2 * F_BOHR2;
        float r6 = rb2 * rb2 * rb2;
        float r8 = r6 * rb2;

        float e = __fdividef(c6, r6 + f6) + F_S8 * __fdividef(c8, r8 + f8);

        float x = (r_ang - 12.0f) * (1.0f / 3.0f);
        x = __saturatef(x);
        float sw = 1.0f - x * x * (3.0f - 2.0f * x);

        esum = fmaf(e, sw, esum);
    }

    // deterministic block reduce -> g_partial[blk]
    #pragma unroll
    for (int o = 16; o > 0; o >>= 1) esum += __shfl_down_sync(0xffffffffu, esum, o);
    if (lane == 0) s_red[wid] = esum;
    __syncthreads();
    if (t < 32) {
        float v = (t < 16) ? s_red[t] : 0.0f;
        #pragma unroll
        for (int o = 8; o > 0; o >>= 1) v += __shfl_down_sync(0xffffffffu, v, o);
        if (t == 0) g_partial[blk] = v;
    }
    __syncthreads();

    // last-block-finalizes (deterministic fixed-order tree; counter self-resets)
    if (t == 0) {
        __threadfence();
        int old = atomicAdd(&g_cnt, 1);
        s_last = (old == NBLK - 1) ? 1 : 0;
    }
    __syncthreads();
    if (s_last) {
        for (int b2 = 0; b2 < BB; b2++) {
            double v = 0.0;
            if (t < NPERB)
                v = (double)((volatile float*)g_partial)[b2 * NPERB + t];
            #pragma unroll
            for (int o = 16; o > 0; o >>= 1) v += __shfl_down_sync(0xffffffffu, v, o);
            if (lane == 0) s_dred[wid] = v;
            __syncthreads();
            if (t < 32) {
                double u = (t < 16) ? s_dred[t] : 0.0;
                #pragma unroll
                for (int o = 8; o > 0; o >>= 1) u += __shfl_down_sync(0xffffffffu, u, o);
                if (t == 0) out[b2] = (float)(-0.5 * u * (double)F_H2EV);
            }
            __syncthreads();
        }
        if (t == 0) g_cnt = 0;
    }
}

extern "C" void kernel_launch(void* const* d_in, const int* in_sizes, int n_in,
                              void* d_out, int out_size)
{
    const float* coord   = (const float*)d_in[0];
    const int*   numbers = (const int*)  d_in[1];
    const float* rcov    = (const float*)d_in[2];
    const float* r4r2    = (const float*)d_in[3];
    const float* c6ab    = (const float*)d_in[4];
    const float* cn_ref  = (const float*)d_in[5];
    float* out = (float*)d_out;

    cn_kernel    <<<BB * JT, 512>>>(coord, numbers, rcov);
    sort_kernel  <<<BB, 512>>>(coord, numbers, r4r2);
    energy_kernel<<<NBLK, 512>>>(c6ab, cn_ref, out);
}